// round 13
// baseline (speedup 1.0000x reference)
#include <cuda_runtime.h>
#include <cuda_fp16.h>
#include <cstdint>

#define NN 100000
#define DF 64
#define NE 1600000
#define NB ((NN + 1023) / 1024)   // 98 scan blocks
#define MAXD 128                  // degree buckets for row sorting

static constexpr float DTC     = 0.2f;
static constexpr float HALF_DT = 0.1f;
static constexpr float DT6     = 0.2f / 6.0f;

// ---------------- scratch (static device globals) ----------------
__device__ int     g_deg1[NN];          // masked row degree (hop-1 CSR)
__device__ int     g_deg2[NN];          // full row degree   (hop-2 CSR)
__device__ int     g_deg_c[NN];         // full col degree
__device__ int     g_cur1[NN];
__device__ int     g_cur2[NN];
__device__ float   g_dinv_r[NN];        // row factor (applied to row sum)
__device__ float   g_premul[NN];        // mask * dinv_c (folded into u)
__device__ float   g_dd[NN];            // dinv_r * dinv_c (folded into t1)
__device__ int     g_rp1[NN + 1];
__device__ int     g_rp2[NN + 1];
__device__ int     g_part1[NB];
__device__ int     g_part2[NB];
__device__ int     g_ecol1[NE];         // masked CSR cols (~half used)
__device__ int     g_ecol2[NE];         // full CSR cols
__device__ int     g_bs1[MAXD];         // degree-bucket counts/starts (hop-1)
__device__ int     g_bs2[MAXD];
__device__ int     g_bc1[MAXD];         // bucket cursors
__device__ int     g_bc2[MAXD];
__device__ int     g_map1[NN];          // rows sorted by deg1
__device__ int     g_map2[NN];          // rows sorted by deg2
__device__ __half2 g_uh [NN * DF / 2];  // stage input * mask*dinv_c, fp16
__device__ __half2 g_t1h[NN * DF / 2];  // hop-1 out * dinv_r*dinv_c, fp16
__device__ __half2 g_rh [NN * DF / 2];  // fp16 copy of current state r
__device__ float4  g_acc[NN * DF / 4];  // k1 + 2k2 + 2k3

// ---------------- preprocessing ----------------
__global__ void zero_kernel() {
    int i = blockIdx.x * blockDim.x + threadIdx.x;
    if (i < NN) { g_deg1[i] = 0; g_deg2[i] = 0; g_deg_c[i] = 0;
                  g_cur1[i] = 0; g_cur2[i] = 0; }
    if (i < MAXD) { g_bs1[i] = 0; g_bs2[i] = 0; g_bc1[i] = 0; g_bc2[i] = 0; }
}

__global__ void hist_kernel(const int* __restrict__ row, const int* __restrict__ col,
                            const int* __restrict__ mask) {
    int e = blockIdx.x * blockDim.x + threadIdx.x;
    if (e < NE) {
        int r = row[e], c = col[e];
        atomicAdd(&g_deg2[r], 1);
        atomicAdd(&g_deg_c[c], 1);
        if (mask[c]) atomicAdd(&g_deg1[r], 1);
    }
}

__global__ void dinv_kernel(const int* __restrict__ mask) {
    int i = blockIdx.x * blockDim.x + threadIdx.x;
    if (i < NN) {
        int dr = g_deg2[i];
        int dc = g_deg_c[i];
        float ir = dr > 0 ? rsqrtf((float)dr) : 0.0f;
        float ic = dc > 0 ? rsqrtf((float)dc) : 0.0f;
        g_dinv_r[i] = ir;
        g_premul[i] = mask[i] ? ic : 0.0f;
        g_dd[i]     = ir * ic;
        // degree-bucket histogram (for quad-equalizing row sort)
        atomicAdd(&g_bs1[min(g_deg1[i], MAXD - 1)], 1);
        atomicAdd(&g_bs2[min(g_deg2[i], MAXD - 1)], 1);
    }
}

// serial exclusive scan of the two 128-entry bucket arrays (trivial)
__global__ void bucket_scan_kernel() {
    int t = threadIdx.x;
    if (t == 0) {
        int s = 0;
        for (int d = 0; d < MAXD; d++) { int v = g_bs1[d]; g_bs1[d] = s; s += v; }
    } else if (t == 32) {
        int s = 0;
        for (int d = 0; d < MAXD; d++) { int v = g_bs2[d]; g_bs2[d] = s; s += v; }
    }
}

__global__ void bucket_scatter_kernel() {
    int i = blockIdx.x * blockDim.x + threadIdx.x;
    if (i < NN) {
        int d1 = min(g_deg1[i], MAXD - 1);
        g_map1[g_bs1[d1] + atomicAdd(&g_bc1[d1], 1)] = i;
        int d2 = min(g_deg2[i], MAXD - 1);
        g_map2[g_bs2[d2] + atomicAdd(&g_bc2[d2], 1)] = i;
    }
}

// Fused two-level scans for BOTH CSRs (blocks [0,NB) -> CSR1, [NB,2NB) -> CSR2)
__global__ void scan_block_fused() {
    int bb = blockIdx.x;
    int isP2 = (bb >= NB);
    int b = isP2 ? bb - NB : bb;
    const int* __restrict__ deg = isP2 ? g_deg2  : g_deg1;
    int* __restrict__ rp        = isP2 ? g_rp2   : g_rp1;
    int* __restrict__ part      = isP2 ? g_part2 : g_part1;
    __shared__ int wsum[32];
    int t = threadIdx.x, lane = t & 31, wid = t >> 5;
    int i = b * 1024 + t;
    int v = (i < NN) ? deg[i] : 0;
    int incl = v;
    #pragma unroll
    for (int off = 1; off < 32; off <<= 1) {
        int x = __shfl_up_sync(0xffffffffu, incl, off);
        if (lane >= off) incl += x;
    }
    if (lane == 31) wsum[wid] = incl;
    __syncthreads();
    if (wid == 0) {
        int ws = wsum[lane];
        int wincl = ws;
        #pragma unroll
        for (int off = 1; off < 32; off <<= 1) {
            int x = __shfl_up_sync(0xffffffffu, wincl, off);
            if (lane >= off) wincl += x;
        }
        wsum[lane] = wincl - ws;
    }
    __syncthreads();
    int excl = incl - v + wsum[wid];
    if (i < NN) rp[i] = excl;
    if (t == 1023) part[b] = excl + v;
}

__global__ void scan_part_fused() {
    int t = threadIdx.x;
    if (t == 0) {
        int s = 0;
        for (int b = 0; b < NB; b++) { int v = g_part1[b]; g_part1[b] = s; s += v; }
        g_rp1[NN] = s;
    } else if (t == 32) {
        int s = 0;
        for (int b = 0; b < NB; b++) { int v = g_part2[b]; g_part2[b] = s; s += v; }
        g_rp2[NN] = s;
    }
}

__global__ void scan_add_fused() {
    int bb = blockIdx.x;
    int isP2 = (bb >= NB);
    int b = isP2 ? bb - NB : bb;
    int* __restrict__ rp         = isP2 ? g_rp2   : g_rp1;
    const int* __restrict__ part = isP2 ? g_part2 : g_part1;
    int i = b * 1024 + threadIdx.x;
    if (i < NN) rp[i] += part[b];
}

__global__ void scatter_kernel(const int* __restrict__ row, const int* __restrict__ col,
                               const int* __restrict__ mask) {
    int e = blockIdx.x * blockDim.x + threadIdx.x;
    if (e < NE) {
        int r = row[e], c = col[e];
        int p2 = g_rp2[r] + atomicAdd(&g_cur2[r], 1);
        g_ecol2[p2] = c;
        if (mask[c]) {
            int p1 = g_rp1[r] + atomicAdd(&g_cur1[r], 1);
            g_ecol1[p1] = c;
        }
    }
}

// uh = mask*dinv_c * r0; rh = fp16(r0)
__global__ void init_u_kernel(const float* __restrict__ r0) {
    int i = blockIdx.x * blockDim.x + threadIdx.x;   // float2 index
    if (i < NN * DF / 2) {
        int node = i >> 5;
        float p = g_premul[node];
        float2 r = ((const float2*)r0)[i];
        g_uh[i] = __floats2half2_rn(p * r.x, p * r.y);
        g_rh[i] = __floats2half2_rn(r.x, r.y);
    }
}

// ------ gather core: QUARTER-WARP per row (4 rows/warp), uint4 (16B) loads ------
// Rows of a warp come from a degree-sorted map -> the 4 rows have ~equal degree
// and the warp-uniform nmax loop wastes ~nothing.
struct Acc8 { float a0, a1, a2, a3, a4, a5, a6, a7; };

#define QACC(v) \
    { float2 f; \
      f = __half22float2(*(const __half2*)&(v).x); r.a0 += f.x; r.a1 += f.y; \
      f = __half22float2(*(const __half2*)&(v).y); r.a2 += f.x; r.a3 += f.y; \
      f = __half22float2(*(const __half2*)&(v).z); r.a4 += f.x; r.a5 += f.y; \
      f = __half22float2(*(const __half2*)&(v).w); r.a6 += f.x; r.a7 += f.y; }

__device__ __forceinline__ Acc8
row_gather_quarter(const __half2* __restrict__ x, const int* __restrict__ ec,
                   const int* __restrict__ rp, int row, int m) {
    int s = rp[row];
    int n_my = rp[row + 1] - s;
    int t = __shfl_xor_sync(0xffffffffu, n_my, 8);
    int nmax = max(n_my, t);
    t = __shfl_xor_sync(0xffffffffu, nmax, 16);
    nmax = max(nmax, t);
    const char* __restrict__ xb = (const char*)x;
    unsigned moff = m << 4;                       // 16 B per lane
    Acc8 r = {0.f, 0.f, 0.f, 0.f, 0.f, 0.f, 0.f, 0.f};

    for (int j0 = 0; j0 < nmax; j0 += 8) {
        int myidx = j0 + m;
        int c = (myidx < n_my) ? __ldg(&ec[s + myidx]) : 0;
        #pragma unroll
        for (int g = 0; g < 2; g++) {
            int b = j0 + g * 4;
            if (b >= nmax) break;                 // warp-uniform
            int c0 = __shfl_sync(0xffffffffu, c, g * 4 + 0, 8);
            int c1 = __shfl_sync(0xffffffffu, c, g * 4 + 1, 8);
            int c2 = __shfl_sync(0xffffffffu, c, g * 4 + 2, 8);
            int c3 = __shfl_sync(0xffffffffu, c, g * 4 + 3, 8);
            uint4 z = make_uint4(0u, 0u, 0u, 0u);
            uint4 v0 = (b + 0 < n_my) ? __ldg((const uint4*)(xb + (((size_t)c0) << 7) + moff)) : z;
            uint4 v1 = (b + 1 < n_my) ? __ldg((const uint4*)(xb + (((size_t)c1) << 7) + moff)) : z;
            uint4 v2 = (b + 2 < n_my) ? __ldg((const uint4*)(xb + (((size_t)c2) << 7) + moff)) : z;
            uint4 v3 = (b + 3 < n_my) ? __ldg((const uint4*)(xb + (((size_t)c3) << 7) + moff)) : z;
            QACC(v0) QACC(v1) QACC(v2) QACC(v3)
        }
    }
    return r;
}

// hop-1: t1h[row] = dd[row] * sum_{masked e} uh[col_e]   (rows via map1)
__global__ void __launch_bounds__(256)
hop1_kernel() {
    int w = (blockIdx.x * blockDim.x + threadIdx.x) >> 5;
    if (w >= NN / 4) return;
    int lane = threadIdx.x & 31;
    int m = lane & 7;
    int row = g_map1[w * 4 + (lane >> 3)];
    Acc8 r = row_gather_quarter(g_uh, g_ecol1, g_rp1, row, m);
    float sc = g_dd[row];
    __half2 h0 = __floats2half2_rn(sc * r.a0, sc * r.a1);
    __half2 h1 = __floats2half2_rn(sc * r.a2, sc * r.a3);
    __half2 h2 = __floats2half2_rn(sc * r.a4, sc * r.a5);
    __half2 h3 = __floats2half2_rn(sc * r.a6, sc * r.a7);
    ((uint4*)g_t1h)[row * 8 + m] =
        make_uint4(*(const unsigned*)&h0, *(const unsigned*)&h1,
                   *(const unsigned*)&h2, *(const unsigned*)&h3);
}

// hop-2 + RK4 epilogue. v = -dinv_r[row] * sum_e t1h[col_e]   (rows via map2)
// MODE 1 (k1): acc  = v;  u = rh + 0.5*dt*v      (rh = fp16 copy of r)
// MODE 2 (k2): acc += 2v; u = rh + 0.5*dt*v
// MODE 3 (k3): acc += 2v; u = rh +     dt*v
// MODE 4 (k4): rnext = r + dt/6*(acc+v) [fp32];  u = rnext; rh = rnext
template <int MODE>
__global__ void __launch_bounds__(256)
hop2_kernel(const float* __restrict__ rin, float* __restrict__ outparam) {
    int w = (blockIdx.x * blockDim.x + threadIdx.x) >> 5;
    if (w >= NN / 4) return;
    int lane = threadIdx.x & 31;
    int m = lane & 7;
    int row = g_map2[w * 4 + (lane >> 3)];
    Acc8 g = row_gather_quarter(g_t1h, g_ecol2, g_rp2, row, m);
    float sr = g_dinv_r[row];
    float v0 = -sr * g.a0, v1 = -sr * g.a1, v2 = -sr * g.a2, v3 = -sr * g.a3;
    float v4 = -sr * g.a4, v5 = -sr * g.a5, v6 = -sr * g.a6, v7 = -sr * g.a7;

    int o4 = row * 8 + m;                         // uint4 index (uh/rh)
    int oA = row * 16 + 2 * m;                    // float4 index (acc/rin)
    float p = g_premul[row];

    float u0, u1, u2, u3, u4, u5, u6, u7;
    if (MODE == 1) {
        g_acc[oA]     = make_float4(v0, v1, v2, v3);
        g_acc[oA + 1] = make_float4(v4, v5, v6, v7);
        uint4 rh4 = ((const uint4*)g_rh)[o4];
        float2 fa = __half22float2(*(const __half2*)&rh4.x);
        float2 fb = __half22float2(*(const __half2*)&rh4.y);
        float2 fc = __half22float2(*(const __half2*)&rh4.z);
        float2 fd = __half22float2(*(const __half2*)&rh4.w);
        u0 = fa.x + HALF_DT * v0; u1 = fa.y + HALF_DT * v1;
        u2 = fb.x + HALF_DT * v2; u3 = fb.y + HALF_DT * v3;
        u4 = fc.x + HALF_DT * v4; u5 = fc.y + HALF_DT * v5;
        u6 = fd.x + HALF_DT * v6; u7 = fd.y + HALF_DT * v7;
    } else if (MODE == 2 || MODE == 3) {
        float4 a0 = g_acc[oA];
        float4 a1 = g_acc[oA + 1];
        g_acc[oA]     = make_float4(a0.x + 2.f * v0, a0.y + 2.f * v1,
                                    a0.z + 2.f * v2, a0.w + 2.f * v3);
        g_acc[oA + 1] = make_float4(a1.x + 2.f * v4, a1.y + 2.f * v5,
                                    a1.z + 2.f * v6, a1.w + 2.f * v7);
        uint4 rh4 = ((const uint4*)g_rh)[o4];
        float2 fa = __half22float2(*(const __half2*)&rh4.x);
        float2 fb = __half22float2(*(const __half2*)&rh4.y);
        float2 fc = __half22float2(*(const __half2*)&rh4.z);
        float2 fd = __half22float2(*(const __half2*)&rh4.w);
        float cdt = (MODE == 2) ? HALF_DT : DTC;
        u0 = fa.x + cdt * v0; u1 = fa.y + cdt * v1;
        u2 = fb.x + cdt * v2; u3 = fb.y + cdt * v3;
        u4 = fc.x + cdt * v4; u5 = fc.y + cdt * v5;
        u6 = fd.x + cdt * v6; u7 = fd.y + cdt * v7;
    } else {  // MODE 4
        float4 a0 = g_acc[oA];
        float4 a1 = g_acc[oA + 1];
        float4 ra = ((const float4*)rin)[oA];
        float4 rb = ((const float4*)rin)[oA + 1];
        u0 = ra.x + DT6 * (a0.x + v0); u1 = ra.y + DT6 * (a0.y + v1);
        u2 = ra.z + DT6 * (a0.z + v2); u3 = ra.w + DT6 * (a0.w + v3);
        u4 = rb.x + DT6 * (a1.x + v4); u5 = rb.y + DT6 * (a1.y + v5);
        u6 = rb.z + DT6 * (a1.z + v6); u7 = rb.w + DT6 * (a1.w + v7);
        ((float4*)outparam)[oA]     = make_float4(u0, u1, u2, u3);
        ((float4*)outparam)[oA + 1] = make_float4(u4, u5, u6, u7);
        __half2 rh0 = __floats2half2_rn(u0, u1);
        __half2 rh1 = __floats2half2_rn(u2, u3);
        __half2 rh2 = __floats2half2_rn(u4, u5);
        __half2 rh3 = __floats2half2_rn(u6, u7);
        ((uint4*)g_rh)[o4] = make_uint4(*(const unsigned*)&rh0, *(const unsigned*)&rh1,
                                        *(const unsigned*)&rh2, *(const unsigned*)&rh3);
    }
    __half2 h0 = __floats2half2_rn(p * u0, p * u1);
    __half2 h1 = __floats2half2_rn(p * u2, p * u3);
    __half2 h2 = __floats2half2_rn(p * u4, p * u5);
    __half2 h3 = __floats2half2_rn(p * u6, p * u7);
    ((uint4*)g_uh)[o4] = make_uint4(*(const unsigned*)&h0, *(const unsigned*)&h1,
                                    *(const unsigned*)&h2, *(const unsigned*)&h3);
}

// ---------------- launch ----------------
extern "C" void kernel_launch(void* const* d_in, const int* in_sizes, int n_in,
                              void* d_out, int out_size) {
    const float* r0   = (const float*)d_in[0];
    const int*   eidx = (const int*)d_in[1];
    const int*   mask = (const int*)d_in[2];
    const int* row = eidx;
    const int* col = eidx + NE;
    float* out = (float*)d_out;

    // CSR + normalization + degree-sorted row maps
    zero_kernel<<<(NN + 255) / 256, 256>>>();
    hist_kernel<<<(NE + 255) / 256, 256>>>(row, col, mask);
    dinv_kernel<<<(NN + 255) / 256, 256>>>(mask);
    bucket_scan_kernel   <<<1, 64>>>();
    bucket_scatter_kernel<<<(NN + 255) / 256, 256>>>();
    scan_block_fused<<<2 * NB, 1024>>>();
    scan_part_fused <<<1, 64>>>();
    scan_add_fused  <<<2 * NB, 1024>>>();
    scatter_kernel  <<<(NE + 255) / 256, 256>>>(row, col, mask);

    // slice 0 = r0; uh = premul * r0; rh = fp16(r0)
    cudaMemcpyAsync(out, r0, (size_t)NN * DF * sizeof(float),
                    cudaMemcpyDeviceToDevice, 0);
    init_u_kernel<<<(NN * DF / 2 + 255) / 256, 256>>>(r0);

    const int blocks = (NN / 4 * 32 + 255) / 256;  // quarter-warp per row

    for (int step = 0; step < 5; step++) {
        const float* r = out + (size_t)step * NN * DF;
        float* rnext   = out + (size_t)(step + 1) * NN * DF;

        hop1_kernel   <<<blocks, 256>>>();
        hop2_kernel<1><<<blocks, 256>>>(r, nullptr);
        hop1_kernel   <<<blocks, 256>>>();
        hop2_kernel<2><<<blocks, 256>>>(r, nullptr);
        hop1_kernel   <<<blocks, 256>>>();
        hop2_kernel<3><<<blocks, 256>>>(r, nullptr);
        hop1_kernel   <<<blocks, 256>>>();
        hop2_kernel<4><<<blocks, 256>>>(r, rnext);
    }
}

// round 14
// speedup vs baseline: 1.0661x; 1.0661x over previous
#include <cuda_runtime.h>
#include <cuda_fp16.h>
#include <cstdint>

#define NN 100000
#define DF 64
#define NE 1600000
#define NB ((NN + 1023) / 1024)   // 98 scan blocks
#define MAXD 128                  // degree buckets for row sorting

static constexpr float DTC     = 0.2f;
static constexpr float HALF_DT = 0.1f;
static constexpr float DT6     = 0.2f / 6.0f;

// ---------------- scratch (static device globals) ----------------
// original-index-space
__device__ int     g_deg1[NN];          // masked row degree
__device__ int     g_deg2[NN];          // full row degree
__device__ int     g_deg_c[NN];         // full col degree
__device__ float   g_dinv_r[NN];
__device__ float   g_premul[NN];        // mask * dinv_c
__device__ float   g_dd[NN];            // dinv_r * dinv_c
__device__ int     g_bs[MAXD];          // degree-bucket starts (by deg2)
__device__ int     g_bc[MAXD];          // bucket cursors
__device__ int     g_map[NN];           // sorted pos -> original row
__device__ int     g_sortpos[NN];       // original row -> sorted pos
// sorted-index-space (everything the hop mainloop touches)
__device__ int     g_degS1[NN];
__device__ int     g_degS2[NN];
__device__ float   g_dinvS[NN];
__device__ float   g_premulS[NN];
__device__ float   g_ddS[NN];
__device__ int     g_cur1[NN];
__device__ int     g_cur2[NN];
__device__ int     g_rp1[NN + 1];
__device__ int     g_rp2[NN + 1];
__device__ int     g_part1[NB];
__device__ int     g_part2[NB];
__device__ int     g_ecol1[NE];         // masked CSR, cols already sorted-space
__device__ int     g_ecol2[NE];         // full CSR, cols already sorted-space
__device__ __half2 g_uh [NN * DF / 2];  // stage input * mask*dinv_c (sorted)
__device__ __half2 g_t1h[NN * DF / 2];  // hop-1 out (sorted)
__device__ __half2 g_rh [NN * DF / 2];  // fp16 state r (sorted)
__device__ float4  g_acc[NN * DF / 4];  // k1+2k2+2k3 (sorted)

// ---------------- preprocessing ----------------
__global__ void zero_kernel() {
    int i = blockIdx.x * blockDim.x + threadIdx.x;
    if (i < NN) { g_deg1[i] = 0; g_deg2[i] = 0; g_deg_c[i] = 0;
                  g_cur1[i] = 0; g_cur2[i] = 0; }
    if (i < MAXD) { g_bs[i] = 0; g_bc[i] = 0; }
}

__global__ void hist_kernel(const int* __restrict__ row, const int* __restrict__ col,
                            const int* __restrict__ mask) {
    int e = blockIdx.x * blockDim.x + threadIdx.x;
    if (e < NE) {
        int r = row[e], c = col[e];
        atomicAdd(&g_deg2[r], 1);
        atomicAdd(&g_deg_c[c], 1);
        if (mask[c]) atomicAdd(&g_deg1[r], 1);
    }
}

__global__ void dinv_kernel(const int* __restrict__ mask) {
    int i = blockIdx.x * blockDim.x + threadIdx.x;
    if (i < NN) {
        int dr = g_deg2[i];
        int dc = g_deg_c[i];
        float ir = dr > 0 ? rsqrtf((float)dr) : 0.0f;
        float ic = dc > 0 ? rsqrtf((float)dc) : 0.0f;
        g_dinv_r[i] = ir;
        g_premul[i] = mask[i] ? ic : 0.0f;
        g_dd[i]     = ir * ic;
        atomicAdd(&g_bs[min(dr, MAXD - 1)], 1);   // bucket by full degree
    }
}

__global__ void bucket_scan_kernel() {
    if (threadIdx.x == 0) {
        int s = 0;
        for (int d = 0; d < MAXD; d++) { int v = g_bs[d]; g_bs[d] = s; s += v; }
    }
}

// build permutation + gather all row-scalar arrays into sorted space
__global__ void bucket_scatter_kernel() {
    int i = blockIdx.x * blockDim.x + threadIdx.x;
    if (i < NN) {
        int d2 = min(g_deg2[i], MAXD - 1);
        int pos = g_bs[d2] + atomicAdd(&g_bc[d2], 1);
        g_map[pos] = i;
        g_sortpos[i] = pos;
        g_degS1[pos] = g_deg1[i];
        g_degS2[pos] = g_deg2[i];
        g_dinvS[pos] = g_dinv_r[i];
        g_premulS[pos] = g_premul[i];
        g_ddS[pos] = g_dd[i];
    }
}

// Fused two-level scans over SORTED degrees (blocks [0,NB)->CSR1, [NB,2NB)->CSR2)
__global__ void scan_block_fused() {
    int bb = blockIdx.x;
    int isP2 = (bb >= NB);
    int b = isP2 ? bb - NB : bb;
    const int* __restrict__ deg = isP2 ? g_degS2 : g_degS1;
    int* __restrict__ rp        = isP2 ? g_rp2   : g_rp1;
    int* __restrict__ part      = isP2 ? g_part2 : g_part1;
    __shared__ int wsum[32];
    int t = threadIdx.x, lane = t & 31, wid = t >> 5;
    int i = b * 1024 + t;
    int v = (i < NN) ? deg[i] : 0;
    int incl = v;
    #pragma unroll
    for (int off = 1; off < 32; off <<= 1) {
        int x = __shfl_up_sync(0xffffffffu, incl, off);
        if (lane >= off) incl += x;
    }
    if (lane == 31) wsum[wid] = incl;
    __syncthreads();
    if (wid == 0) {
        int ws = wsum[lane];
        int wincl = ws;
        #pragma unroll
        for (int off = 1; off < 32; off <<= 1) {
            int x = __shfl_up_sync(0xffffffffu, wincl, off);
            if (lane >= off) wincl += x;
        }
        wsum[lane] = wincl - ws;
    }
    __syncthreads();
    int excl = incl - v + wsum[wid];
    if (i < NN) rp[i] = excl;
    if (t == 1023) part[b] = excl + v;
}

__global__ void scan_part_fused() {
    int t = threadIdx.x;
    if (t == 0) {
        int s = 0;
        for (int b = 0; b < NB; b++) { int v = g_part1[b]; g_part1[b] = s; s += v; }
        g_rp1[NN] = s;
    } else if (t == 32) {
        int s = 0;
        for (int b = 0; b < NB; b++) { int v = g_part2[b]; g_part2[b] = s; s += v; }
        g_rp2[NN] = s;
    }
}

__global__ void scan_add_fused() {
    int bb = blockIdx.x;
    int isP2 = (bb >= NB);
    int b = isP2 ? bb - NB : bb;
    int* __restrict__ rp         = isP2 ? g_rp2   : g_rp1;
    const int* __restrict__ part = isP2 ? g_part2 : g_part1;
    int i = b * 1024 + threadIdx.x;
    if (i < NN) rp[i] += part[b];
}

// Build CSRs directly in sorted space (rows AND columns remapped)
__global__ void scatter_kernel(const int* __restrict__ row, const int* __restrict__ col,
                               const int* __restrict__ mask) {
    int e = blockIdx.x * blockDim.x + threadIdx.x;
    if (e < NE) {
        int r = row[e], c = col[e];
        int sr = g_sortpos[r];
        int sc = g_sortpos[c];
        int p2 = g_rp2[sr] + atomicAdd(&g_cur2[sr], 1);
        g_ecol2[p2] = sc;
        if (mask[c]) {
            int p1 = g_rp1[sr] + atomicAdd(&g_cur1[sr], 1);
            g_ecol1[p1] = sc;
        }
    }
}

// uh/rh (sorted space) from r0 (original space). One warp per sorted node.
__global__ void init_u_kernel(const float* __restrict__ r0) {
    int i = blockIdx.x * blockDim.x + threadIdx.x;   // sorted float2 index
    if (i < NN * DF / 2) {
        int spos = i >> 5;
        int lane = i & 31;
        int orig = g_map[spos];
        float p = g_premulS[spos];
        float2 r = ((const float2*)r0)[orig * 32 + lane];
        g_uh[i] = __floats2half2_rn(p * r.x, p * r.y);
        g_rh[i] = __floats2half2_rn(r.x, r.y);
    }
}

// ------ gather core: QUARTER-WARP per row (4 rows/warp), uint4 (16B) loads ------
// Rows are degree-sorted, so the 4 rows/warp have ~equal degree -> nmax ~ n_my.
struct Acc8 { float a0, a1, a2, a3, a4, a5, a6, a7; };

#define QACC(v) \
    { float2 f; \
      f = __half22float2(*(const __half2*)&(v).x); r.a0 += f.x; r.a1 += f.y; \
      f = __half22float2(*(const __half2*)&(v).y); r.a2 += f.x; r.a3 += f.y; \
      f = __half22float2(*(const __half2*)&(v).z); r.a4 += f.x; r.a5 += f.y; \
      f = __half22float2(*(const __half2*)&(v).w); r.a6 += f.x; r.a7 += f.y; }

__device__ __forceinline__ Acc8
row_gather_quarter(const __half2* __restrict__ x, const int* __restrict__ ec,
                   const int* __restrict__ rp, int row, int m) {
    int s = rp[row];
    int n_my = rp[row + 1] - s;
    int t = __shfl_xor_sync(0xffffffffu, n_my, 8);
    int nmax = max(n_my, t);
    t = __shfl_xor_sync(0xffffffffu, nmax, 16);
    nmax = max(nmax, t);
    const char* __restrict__ xb = (const char*)x;
    unsigned moff = m << 4;                       // 16 B per lane
    Acc8 r = {0.f, 0.f, 0.f, 0.f, 0.f, 0.f, 0.f, 0.f};

    for (int j0 = 0; j0 < nmax; j0 += 8) {
        int myidx = j0 + m;
        int c = (myidx < n_my) ? __ldg(&ec[s + myidx]) : 0;
        #pragma unroll
        for (int g = 0; g < 2; g++) {
            int b = j0 + g * 4;
            if (b >= nmax) break;                 // warp-uniform
            int c0 = __shfl_sync(0xffffffffu, c, g * 4 + 0, 8);
            int c1 = __shfl_sync(0xffffffffu, c, g * 4 + 1, 8);
            int c2 = __shfl_sync(0xffffffffu, c, g * 4 + 2, 8);
            int c3 = __shfl_sync(0xffffffffu, c, g * 4 + 3, 8);
            uint4 z = make_uint4(0u, 0u, 0u, 0u);
            uint4 v0 = (b + 0 < n_my) ? __ldg((const uint4*)(xb + (((size_t)c0) << 7) + moff)) : z;
            uint4 v1 = (b + 1 < n_my) ? __ldg((const uint4*)(xb + (((size_t)c1) << 7) + moff)) : z;
            uint4 v2 = (b + 2 < n_my) ? __ldg((const uint4*)(xb + (((size_t)c2) << 7) + moff)) : z;
            uint4 v3 = (b + 3 < n_my) ? __ldg((const uint4*)(xb + (((size_t)c3) << 7) + moff)) : z;
            QACC(v0) QACC(v1) QACC(v2) QACC(v3)
        }
    }
    return r;
}

// hop-1: t1h[row] = ddS[row] * sum_{masked e} uh[col_e]   (all sorted space)
__global__ void __launch_bounds__(256)
hop1_kernel() {
    int w = (blockIdx.x * blockDim.x + threadIdx.x) >> 5;
    if (w >= NN / 4) return;
    int lane = threadIdx.x & 31;
    int m = lane & 7;
    int row = w * 4 + (lane >> 3);
    Acc8 r = row_gather_quarter(g_uh, g_ecol1, g_rp1, row, m);
    float sc = g_ddS[row];
    __half2 h0 = __floats2half2_rn(sc * r.a0, sc * r.a1);
    __half2 h1 = __floats2half2_rn(sc * r.a2, sc * r.a3);
    __half2 h2 = __floats2half2_rn(sc * r.a4, sc * r.a5);
    __half2 h3 = __floats2half2_rn(sc * r.a6, sc * r.a7);
    ((uint4*)g_t1h)[row * 8 + m] =
        make_uint4(*(const unsigned*)&h0, *(const unsigned*)&h1,
                   *(const unsigned*)&h2, *(const unsigned*)&h3);
}

// hop-2 + RK4 epilogue (sorted space; mode 4 additionally touches original
// space for rin/outparam via g_map).
template <int MODE>
__global__ void __launch_bounds__(256)
hop2_kernel(const float* __restrict__ rin, float* __restrict__ outparam) {
    int w = (blockIdx.x * blockDim.x + threadIdx.x) >> 5;
    if (w >= NN / 4) return;
    int lane = threadIdx.x & 31;
    int m = lane & 7;
    int row = w * 4 + (lane >> 3);
    Acc8 g = row_gather_quarter(g_t1h, g_ecol2, g_rp2, row, m);
    float sr = g_dinvS[row];
    float v0 = -sr * g.a0, v1 = -sr * g.a1, v2 = -sr * g.a2, v3 = -sr * g.a3;
    float v4 = -sr * g.a4, v5 = -sr * g.a5, v6 = -sr * g.a6, v7 = -sr * g.a7;

    int o4 = row * 8 + m;                         // uint4 index (uh/rh, sorted)
    int oA = row * 16 + 2 * m;                    // float4 index (acc, sorted)
    float p = g_premulS[row];

    float u0, u1, u2, u3, u4, u5, u6, u7;
    if (MODE == 1) {
        g_acc[oA]     = make_float4(v0, v1, v2, v3);
        g_acc[oA + 1] = make_float4(v4, v5, v6, v7);
        uint4 rh4 = ((const uint4*)g_rh)[o4];
        float2 fa = __half22float2(*(const __half2*)&rh4.x);
        float2 fb = __half22float2(*(const __half2*)&rh4.y);
        float2 fc = __half22float2(*(const __half2*)&rh4.z);
        float2 fd = __half22float2(*(const __half2*)&rh4.w);
        u0 = fa.x + HALF_DT * v0; u1 = fa.y + HALF_DT * v1;
        u2 = fb.x + HALF_DT * v2; u3 = fb.y + HALF_DT * v3;
        u4 = fc.x + HALF_DT * v4; u5 = fc.y + HALF_DT * v5;
        u6 = fd.x + HALF_DT * v6; u7 = fd.y + HALF_DT * v7;
    } else if (MODE == 2 || MODE == 3) {
        float4 a0 = g_acc[oA];
        float4 a1 = g_acc[oA + 1];
        g_acc[oA]     = make_float4(a0.x + 2.f * v0, a0.y + 2.f * v1,
                                    a0.z + 2.f * v2, a0.w + 2.f * v3);
        g_acc[oA + 1] = make_float4(a1.x + 2.f * v4, a1.y + 2.f * v5,
                                    a1.z + 2.f * v6, a1.w + 2.f * v7);
        uint4 rh4 = ((const uint4*)g_rh)[o4];
        float2 fa = __half22float2(*(const __half2*)&rh4.x);
        float2 fb = __half22float2(*(const __half2*)&rh4.y);
        float2 fc = __half22float2(*(const __half2*)&rh4.z);
        float2 fd = __half22float2(*(const __half2*)&rh4.w);
        float cdt = (MODE == 2) ? HALF_DT : DTC;
        u0 = fa.x + cdt * v0; u1 = fa.y + cdt * v1;
        u2 = fb.x + cdt * v2; u3 = fb.y + cdt * v3;
        u4 = fc.x + cdt * v4; u5 = fc.y + cdt * v5;
        u6 = fd.x + cdt * v6; u7 = fd.y + cdt * v7;
    } else {  // MODE 4: original-space rin/out
        float4 a0 = g_acc[oA];
        float4 a1 = g_acc[oA + 1];
        int orig = g_map[row];
        int oR = orig * 16 + 2 * m;
        float4 ra = ((const float4*)rin)[oR];
        float4 rb = ((const float4*)rin)[oR + 1];
        u0 = ra.x + DT6 * (a0.x + v0); u1 = ra.y + DT6 * (a0.y + v1);
        u2 = ra.z + DT6 * (a0.z + v2); u3 = ra.w + DT6 * (a0.w + v3);
        u4 = rb.x + DT6 * (a1.x + v4); u5 = rb.y + DT6 * (a1.y + v5);
        u6 = rb.z + DT6 * (a1.z + v6); u7 = rb.w + DT6 * (a1.w + v7);
        ((float4*)outparam)[oR]     = make_float4(u0, u1, u2, u3);
        ((float4*)outparam)[oR + 1] = make_float4(u4, u5, u6, u7);
        __half2 rh0 = __floats2half2_rn(u0, u1);
        __half2 rh1 = __floats2half2_rn(u2, u3);
        __half2 rh2 = __floats2half2_rn(u4, u5);
        __half2 rh3 = __floats2half2_rn(u6, u7);
        ((uint4*)g_rh)[o4] = make_uint4(*(const unsigned*)&rh0, *(const unsigned*)&rh1,
                                        *(const unsigned*)&rh2, *(const unsigned*)&rh3);
    }
    __half2 h0 = __floats2half2_rn(p * u0, p * u1);
    __half2 h1 = __floats2half2_rn(p * u2, p * u3);
    __half2 h2 = __floats2half2_rn(p * u4, p * u5);
    __half2 h3 = __floats2half2_rn(p * u6, p * u7);
    ((uint4*)g_uh)[o4] = make_uint4(*(const unsigned*)&h0, *(const unsigned*)&h1,
                                    *(const unsigned*)&h2, *(const unsigned*)&h3);
}

// ---------------- launch ----------------
extern "C" void kernel_launch(void* const* d_in, const int* in_sizes, int n_in,
                              void* d_out, int out_size) {
    const float* r0   = (const float*)d_in[0];
    const int*   eidx = (const int*)d_in[1];
    const int*   mask = (const int*)d_in[2];
    const int* row = eidx;
    const int* col = eidx + NE;
    float* out = (float*)d_out;

    // permutation + CSR (in sorted space) + normalization
    zero_kernel<<<(NN + 255) / 256, 256>>>();
    hist_kernel<<<(NE + 255) / 256, 256>>>(row, col, mask);
    dinv_kernel<<<(NN + 255) / 256, 256>>>(mask);
    bucket_scan_kernel   <<<1, 32>>>();
    bucket_scatter_kernel<<<(NN + 255) / 256, 256>>>();
    scan_block_fused<<<2 * NB, 1024>>>();
    scan_part_fused <<<1, 64>>>();
    scan_add_fused  <<<2 * NB, 1024>>>();
    scatter_kernel  <<<(NE + 255) / 256, 256>>>(row, col, mask);

    // slice 0 = r0; uh/rh (sorted) from r0
    cudaMemcpyAsync(out, r0, (size_t)NN * DF * sizeof(float),
                    cudaMemcpyDeviceToDevice, 0);
    init_u_kernel<<<(NN * DF / 2 + 255) / 256, 256>>>(r0);

    const int blocks = (NN / 4 * 32 + 255) / 256;  // quarter-warp per row

    for (int step = 0; step < 5; step++) {
        const float* r = out + (size_t)step * NN * DF;
        float* rnext   = out + (size_t)(step + 1) * NN * DF;

        hop1_kernel   <<<blocks, 256>>>();
        hop2_kernel<1><<<blocks, 256>>>(r, nullptr);
        hop1_kernel   <<<blocks, 256>>>();
        hop2_kernel<2><<<blocks, 256>>>(r, nullptr);
        hop1_kernel   <<<blocks, 256>>>();
        hop2_kernel<3><<<blocks, 256>>>(r, nullptr);
        hop1_kernel   <<<blocks, 256>>>();
        hop2_kernel<4><<<blocks, 256>>>(r, rnext);
    }
}

// round 15
// speedup vs baseline: 1.1191x; 1.0498x over previous
#include <cuda_runtime.h>
#include <cuda_fp16.h>
#include <cstdint>

#define NN 100000
#define DF 64
#define NE 1600000
#define NB ((NN + 1023) / 1024)   // 98 scan blocks

static constexpr float DTC     = 0.2f;
static constexpr float HALF_DT = 0.1f;
static constexpr float DT6     = 0.2f / 6.0f;

// ---------------- scratch (static device globals) ----------------
__device__ int     g_deg1[NN];          // masked row degree (hop-1 CSR)
__device__ int     g_deg2[NN];          // full row degree   (hop-2 CSR)
__device__ int     g_deg_c[NN];         // full col degree
__device__ int     g_cur1[NN];
__device__ int     g_cur2[NN];
__device__ float   g_dinv_r[NN];        // row factor (applied to row sum)
__device__ float   g_premul[NN];        // mask * dinv_c (folded into u)
__device__ float   g_dd[NN];            // dinv_r * dinv_c (folded into t1)
__device__ int     g_rp1[NN + 1];
__device__ int     g_rp2[NN + 1];
__device__ int     g_part1[NB];
__device__ int     g_part2[NB];
__device__ int     g_ecol1[NE];         // masked CSR cols (~half used)
__device__ int     g_ecol2[NE];         // full CSR cols
__device__ __half2 g_uh [NN * DF / 2];  // stage input * mask*dinv_c, fp16
__device__ __half2 g_t1h[NN * DF / 2];  // hop-1 out * dinv_r*dinv_c, fp16
__device__ __half2 g_rh [NN * DF / 2];  // fp16 copy of current state r
__device__ float4  g_acc[NN * DF / 4];  // k1 + 2k2 + 2k3

// ---------------- preprocessing ----------------
__global__ void zero_kernel() {
    int i = blockIdx.x * blockDim.x + threadIdx.x;
    if (i < NN) { g_deg1[i] = 0; g_deg2[i] = 0; g_deg_c[i] = 0;
                  g_cur1[i] = 0; g_cur2[i] = 0; }
}

__global__ void hist_kernel(const int* __restrict__ row, const int* __restrict__ col,
                            const int* __restrict__ mask) {
    int e = blockIdx.x * blockDim.x + threadIdx.x;
    if (e < NE) {
        int r = row[e], c = col[e];
        atomicAdd(&g_deg2[r], 1);
        atomicAdd(&g_deg_c[c], 1);
        if (mask[c]) atomicAdd(&g_deg1[r], 1);
    }
}

__global__ void dinv_kernel(const int* __restrict__ mask) {
    int i = blockIdx.x * blockDim.x + threadIdx.x;
    if (i < NN) {
        int dr = g_deg2[i];
        int dc = g_deg_c[i];
        float ir = dr > 0 ? rsqrtf((float)dr) : 0.0f;
        float ic = dc > 0 ? rsqrtf((float)dc) : 0.0f;
        g_dinv_r[i] = ir;
        g_premul[i] = mask[i] ? ic : 0.0f;
        g_dd[i]     = ir * ic;
    }
}

// Fused two-level scans for BOTH CSRs (blocks [0,NB) -> CSR1, [NB,2NB) -> CSR2)
__global__ void scan_block_fused() {
    int bb = blockIdx.x;
    int isP2 = (bb >= NB);
    int b = isP2 ? bb - NB : bb;
    const int* __restrict__ deg = isP2 ? g_deg2  : g_deg1;
    int* __restrict__ rp        = isP2 ? g_rp2   : g_rp1;
    int* __restrict__ part      = isP2 ? g_part2 : g_part1;
    __shared__ int wsum[32];
    int t = threadIdx.x, lane = t & 31, wid = t >> 5;
    int i = b * 1024 + t;
    int v = (i < NN) ? deg[i] : 0;
    int incl = v;
    #pragma unroll
    for (int off = 1; off < 32; off <<= 1) {
        int x = __shfl_up_sync(0xffffffffu, incl, off);
        if (lane >= off) incl += x;
    }
    if (lane == 31) wsum[wid] = incl;
    __syncthreads();
    if (wid == 0) {
        int ws = wsum[lane];
        int wincl = ws;
        #pragma unroll
        for (int off = 1; off < 32; off <<= 1) {
            int x = __shfl_up_sync(0xffffffffu, wincl, off);
            if (lane >= off) wincl += x;
        }
        wsum[lane] = wincl - ws;
    }
    __syncthreads();
    int excl = incl - v + wsum[wid];
    if (i < NN) rp[i] = excl;
    if (t == 1023) part[b] = excl + v;
}

__global__ void scan_part_fused() {
    int t = threadIdx.x;
    if (t == 0) {
        int s = 0;
        for (int b = 0; b < NB; b++) { int v = g_part1[b]; g_part1[b] = s; s += v; }
        g_rp1[NN] = s;
    } else if (t == 32) {
        int s = 0;
        for (int b = 0; b < NB; b++) { int v = g_part2[b]; g_part2[b] = s; s += v; }
        g_rp2[NN] = s;
    }
}

__global__ void scan_add_fused() {
    int bb = blockIdx.x;
    int isP2 = (bb >= NB);
    int b = isP2 ? bb - NB : bb;
    int* __restrict__ rp         = isP2 ? g_rp2   : g_rp1;
    const int* __restrict__ part = isP2 ? g_part2 : g_part1;
    int i = b * 1024 + threadIdx.x;
    if (i < NN) rp[i] += part[b];
}

__global__ void scatter_kernel(const int* __restrict__ row, const int* __restrict__ col,
                               const int* __restrict__ mask) {
    int e = blockIdx.x * blockDim.x + threadIdx.x;
    if (e < NE) {
        int r = row[e], c = col[e];
        int p2 = g_rp2[r] + atomicAdd(&g_cur2[r], 1);
        g_ecol2[p2] = c;
        if (mask[c]) {
            int p1 = g_rp1[r] + atomicAdd(&g_cur1[r], 1);
            g_ecol1[p1] = c;
        }
    }
}

// uh = mask*dinv_c * r0; rh = fp16(r0)
__global__ void init_u_kernel(const float* __restrict__ r0) {
    int i = blockIdx.x * blockDim.x + threadIdx.x;   // float2 index
    if (i < NN * DF / 2) {
        int node = i >> 5;
        float p = g_premul[node];
        float2 r = ((const float2*)r0)[i];
        g_uh[i] = __floats2half2_rn(p * r.x, p * r.y);
        g_rh[i] = __floats2half2_rn(r.x, r.y);
    }
}

// ------ gather core: QUARTER-WARP per row (4 rows/warp), uint4 (16B) loads ------
// Lane m (0..7) of quarter q owns features 8m..8m+7 of row 4w+q. One LDG.128
// warp-instruction gathers one edge for each of the 4 rows. Warp-uniform loop
// to nmax (max degree of the quad); shorter rows' loads predicated to zero.
struct Acc8 { float a0, a1, a2, a3, a4, a5, a6, a7; };

#define QACC(v) \
    { float2 f; \
      f = __half22float2(*(const __half2*)&(v).x); r.a0 += f.x; r.a1 += f.y; \
      f = __half22float2(*(const __half2*)&(v).y); r.a2 += f.x; r.a3 += f.y; \
      f = __half22float2(*(const __half2*)&(v).z); r.a4 += f.x; r.a5 += f.y; \
      f = __half22float2(*(const __half2*)&(v).w); r.a6 += f.x; r.a7 += f.y; }

__device__ __forceinline__ Acc8
row_gather_quarter(const __half2* __restrict__ x, const int* __restrict__ ec,
                   const int* __restrict__ rp, int row, int m) {
    int s = rp[row];
    int n_my = rp[row + 1] - s;
    int t = __shfl_xor_sync(0xffffffffu, n_my, 8);
    int nmax = max(n_my, t);
    t = __shfl_xor_sync(0xffffffffu, nmax, 16);
    nmax = max(nmax, t);
    const char* __restrict__ xb = (const char*)x;
    unsigned moff = m << 4;                       // 16 B per lane
    Acc8 r = {0.f, 0.f, 0.f, 0.f, 0.f, 0.f, 0.f, 0.f};

    for (int j0 = 0; j0 < nmax; j0 += 8) {
        int myidx = j0 + m;
        int c = (myidx < n_my) ? __ldg(&ec[s + myidx]) : 0;
        #pragma unroll
        for (int g = 0; g < 2; g++) {
            int b = j0 + g * 4;
            if (b >= nmax) break;                 // warp-uniform
            int c0 = __shfl_sync(0xffffffffu, c, g * 4 + 0, 8);
            int c1 = __shfl_sync(0xffffffffu, c, g * 4 + 1, 8);
            int c2 = __shfl_sync(0xffffffffu, c, g * 4 + 2, 8);
            int c3 = __shfl_sync(0xffffffffu, c, g * 4 + 3, 8);
            uint4 z = make_uint4(0u, 0u, 0u, 0u);
            uint4 v0 = (b + 0 < n_my) ? __ldg((const uint4*)(xb + (((size_t)c0) << 7) + moff)) : z;
            uint4 v1 = (b + 1 < n_my) ? __ldg((const uint4*)(xb + (((size_t)c1) << 7) + moff)) : z;
            uint4 v2 = (b + 2 < n_my) ? __ldg((const uint4*)(xb + (((size_t)c2) << 7) + moff)) : z;
            uint4 v3 = (b + 3 < n_my) ? __ldg((const uint4*)(xb + (((size_t)c3) << 7) + moff)) : z;
            QACC(v0) QACC(v1) QACC(v2) QACC(v3)
        }
    }
    return r;
}

// hop-1: t1h[row] = dd[row] * sum_{masked e} uh[col_e]
__global__ void __launch_bounds__(64)
hop1_kernel() {
    int w = (blockIdx.x * blockDim.x + threadIdx.x) >> 5;
    if (w >= NN / 4) return;
    int lane = threadIdx.x & 31;
    int m = lane & 7;
    int row = w * 4 + (lane >> 3);
    Acc8 r = row_gather_quarter(g_uh, g_ecol1, g_rp1, row, m);
    float sc = g_dd[row];
    __half2 h0 = __floats2half2_rn(sc * r.a0, sc * r.a1);
    __half2 h1 = __floats2half2_rn(sc * r.a2, sc * r.a3);
    __half2 h2 = __floats2half2_rn(sc * r.a4, sc * r.a5);
    __half2 h3 = __floats2half2_rn(sc * r.a6, sc * r.a7);
    ((uint4*)g_t1h)[row * 8 + m] =
        make_uint4(*(const unsigned*)&h0, *(const unsigned*)&h1,
                   *(const unsigned*)&h2, *(const unsigned*)&h3);
}

// hop-2 + RK4 epilogue. v = -dinv_r[row] * sum_e t1h[col_e]
// MODE 1 (k1): acc  = v;  u = rh + 0.5*dt*v      (rh = fp16 copy of r)
// MODE 2 (k2): acc += 2v; u = rh + 0.5*dt*v
// MODE 3 (k3): acc += 2v; u = rh +     dt*v
// MODE 4 (k4): rnext = r + dt/6*(acc+v) [fp32];  u = rnext; rh = rnext
template <int MODE>
__global__ void __launch_bounds__(64)
hop2_kernel(const float* __restrict__ rin, float* __restrict__ outparam) {
    int w = (blockIdx.x * blockDim.x + threadIdx.x) >> 5;
    if (w >= NN / 4) return;
    int lane = threadIdx.x & 31;
    int m = lane & 7;
    int row = w * 4 + (lane >> 3);
    Acc8 g = row_gather_quarter(g_t1h, g_ecol2, g_rp2, row, m);
    float sr = g_dinv_r[row];
    float v0 = -sr * g.a0, v1 = -sr * g.a1, v2 = -sr * g.a2, v3 = -sr * g.a3;
    float v4 = -sr * g.a4, v5 = -sr * g.a5, v6 = -sr * g.a6, v7 = -sr * g.a7;

    int o4 = row * 8 + m;                         // uint4 index (uh/rh)
    int oA = row * 16 + 2 * m;                    // float4 index (acc/rin)
    float p = g_premul[row];

    float u0, u1, u2, u3, u4, u5, u6, u7;
    if (MODE == 1) {
        g_acc[oA]     = make_float4(v0, v1, v2, v3);
        g_acc[oA + 1] = make_float4(v4, v5, v6, v7);
        uint4 rh4 = ((const uint4*)g_rh)[o4];
        float2 fa = __half22float2(*(const __half2*)&rh4.x);
        float2 fb = __half22float2(*(const __half2*)&rh4.y);
        float2 fc = __half22float2(*(const __half2*)&rh4.z);
        float2 fd = __half22float2(*(const __half2*)&rh4.w);
        u0 = fa.x + HALF_DT * v0; u1 = fa.y + HALF_DT * v1;
        u2 = fb.x + HALF_DT * v2; u3 = fb.y + HALF_DT * v3;
        u4 = fc.x + HALF_DT * v4; u5 = fc.y + HALF_DT * v5;
        u6 = fd.x + HALF_DT * v6; u7 = fd.y + HALF_DT * v7;
    } else if (MODE == 2 || MODE == 3) {
        float4 a0 = g_acc[oA];
        float4 a1 = g_acc[oA + 1];
        g_acc[oA]     = make_float4(a0.x + 2.f * v0, a0.y + 2.f * v1,
                                    a0.z + 2.f * v2, a0.w + 2.f * v3);
        g_acc[oA + 1] = make_float4(a1.x + 2.f * v4, a1.y + 2.f * v5,
                                    a1.z + 2.f * v6, a1.w + 2.f * v7);
        uint4 rh4 = ((const uint4*)g_rh)[o4];
        float2 fa = __half22float2(*(const __half2*)&rh4.x);
        float2 fb = __half22float2(*(const __half2*)&rh4.y);
        float2 fc = __half22float2(*(const __half2*)&rh4.z);
        float2 fd = __half22float2(*(const __half2*)&rh4.w);
        float cdt = (MODE == 2) ? HALF_DT : DTC;
        u0 = fa.x + cdt * v0; u1 = fa.y + cdt * v1;
        u2 = fb.x + cdt * v2; u3 = fb.y + cdt * v3;
        u4 = fc.x + cdt * v4; u5 = fc.y + cdt * v5;
        u6 = fd.x + cdt * v6; u7 = fd.y + cdt * v7;
    } else {  // MODE 4
        float4 a0 = g_acc[oA];
        float4 a1 = g_acc[oA + 1];
        float4 ra = ((const float4*)rin)[oA];
        float4 rb = ((const float4*)rin)[oA + 1];
        u0 = ra.x + DT6 * (a0.x + v0); u1 = ra.y + DT6 * (a0.y + v1);
        u2 = ra.z + DT6 * (a0.z + v2); u3 = ra.w + DT6 * (a0.w + v3);
        u4 = rb.x + DT6 * (a1.x + v4); u5 = rb.y + DT6 * (a1.y + v5);
        u6 = rb.z + DT6 * (a1.z + v6); u7 = rb.w + DT6 * (a1.w + v7);
        ((float4*)outparam)[oA]     = make_float4(u0, u1, u2, u3);
        ((float4*)outparam)[oA + 1] = make_float4(u4, u5, u6, u7);
        __half2 rh0 = __floats2half2_rn(u0, u1);
        __half2 rh1 = __floats2half2_rn(u2, u3);
        __half2 rh2 = __floats2half2_rn(u4, u5);
        __half2 rh3 = __floats2half2_rn(u6, u7);
        ((uint4*)g_rh)[o4] = make_uint4(*(const unsigned*)&rh0, *(const unsigned*)&rh1,
                                        *(const unsigned*)&rh2, *(const unsigned*)&rh3);
    }
    __half2 h0 = __floats2half2_rn(p * u0, p * u1);
    __half2 h1 = __floats2half2_rn(p * u2, p * u3);
    __half2 h2 = __floats2half2_rn(p * u4, p * u5);
    __half2 h3 = __floats2half2_rn(p * u6, p * u7);
    ((uint4*)g_uh)[o4] = make_uint4(*(const unsigned*)&h0, *(const unsigned*)&h1,
                                    *(const unsigned*)&h2, *(const unsigned*)&h3);
}

// ---------------- launch ----------------
extern "C" void kernel_launch(void* const* d_in, const int* in_sizes, int n_in,
                              void* d_out, int out_size) {
    const float* r0   = (const float*)d_in[0];
    const int*   eidx = (const int*)d_in[1];
    const int*   mask = (const int*)d_in[2];
    const int* row = eidx;
    const int* col = eidx + NE;
    float* out = (float*)d_out;

    // CSR + normalization build (no device-global symbols passed from host!)
    zero_kernel<<<(NN + 255) / 256, 256>>>();
    hist_kernel<<<(NE + 255) / 256, 256>>>(row, col, mask);
    dinv_kernel<<<(NN + 255) / 256, 256>>>(mask);
    scan_block_fused<<<2 * NB, 1024>>>();
    scan_part_fused <<<1, 64>>>();
    scan_add_fused  <<<2 * NB, 1024>>>();
    scatter_kernel  <<<(NE + 255) / 256, 256>>>(row, col, mask);

    // slice 0 = r0; uh = premul * r0; rh = fp16(r0)
    cudaMemcpyAsync(out, r0, (size_t)NN * DF * sizeof(float),
                    cudaMemcpyDeviceToDevice, 0);
    init_u_kernel<<<(NN * DF / 2 + 255) / 256, 256>>>(r0);

    // quarter-warp per row; SMALL blocks (64 thr = 8 rows) to shrink the
    // end-of-grid scheduling tail (t_block ~4x smaller than 256-thr blocks)
    const int blocks = (NN / 4 * 32 + 63) / 64;

    for (int step = 0; step < 5; step++) {
        const float* r = out + (size_t)step * NN * DF;
        float* rnext   = out + (size_t)(step + 1) * NN * DF;

        hop1_kernel   <<<blocks, 64>>>();
        hop2_kernel<1><<<blocks, 64>>>(r, nullptr);
        hop1_kernel   <<<blocks, 64>>>();
        hop2_kernel<2><<<blocks, 64>>>(r, nullptr);
        hop1_kernel   <<<blocks, 64>>>();
        hop2_kernel<3><<<blocks, 64>>>(r, nullptr);
        hop1_kernel   <<<blocks, 64>>>();
        hop2_kernel<4><<<blocks, 64>>>(r, rnext);
    }
}

// round 16
// speedup vs baseline: 1.1460x; 1.0240x over previous
#include <cuda_runtime.h>
#include <cuda_fp16.h>
#include <cstdint>

#define NN 100000
#define DF 64
#define NE 1600000
#define NB ((NN + 1023) / 1024)   // 98 scan blocks

static constexpr float DTC     = 0.2f;
static constexpr float HALF_DT = 0.1f;
static constexpr float DT6     = 0.2f / 6.0f;

// ---------------- scratch (static device globals) ----------------
__device__ int     g_deg1[NN];          // masked row degree (hop-1 CSR)
__device__ int     g_deg2[NN];          // full row degree   (hop-2 CSR)
__device__ int     g_deg_c[NN];         // full col degree
__device__ int     g_cur1[NN];
__device__ int     g_cur2[NN];
__device__ float   g_dinv_r[NN];        // row factor (applied to row sum)
__device__ float   g_premul[NN];        // mask * dinv_c (folded into u)
__device__ float   g_dd[NN];            // dinv_r * dinv_c (folded into t1)
__device__ int     g_rp1[NN + 1];
__device__ int     g_rp2[NN + 1];
__device__ int     g_part1[NB];
__device__ int     g_part2[NB];
__device__ int     g_ecol1[NE];         // masked CSR cols (~half used)
__device__ int     g_ecol2[NE];         // full CSR cols
__device__ __half2 g_uh [NN * DF / 2];  // stage input * mask*dinv_c, fp16
__device__ __half2 g_t1h[NN * DF / 2];  // hop-1 out * dinv_r*dinv_c, fp16
__device__ __half2 g_rh [NN * DF / 2];  // fp16 copy of current state r
__device__ uint4   g_acch[NN * DF / 8]; // k1 + 2k2 + 2k3, fp16 (4x half2)

// ---------------- preprocessing ----------------
__global__ void zero_kernel() {
    int i = blockIdx.x * blockDim.x + threadIdx.x;
    if (i < NN) { g_deg1[i] = 0; g_deg2[i] = 0; g_deg_c[i] = 0;
                  g_cur1[i] = 0; g_cur2[i] = 0; }
}

__global__ void hist_kernel(const int* __restrict__ row, const int* __restrict__ col,
                            const int* __restrict__ mask) {
    int e = blockIdx.x * blockDim.x + threadIdx.x;
    if (e < NE) {
        int r = row[e], c = col[e];
        atomicAdd(&g_deg2[r], 1);
        atomicAdd(&g_deg_c[c], 1);
        if (mask[c]) atomicAdd(&g_deg1[r], 1);
    }
}

__global__ void dinv_kernel(const int* __restrict__ mask) {
    int i = blockIdx.x * blockDim.x + threadIdx.x;
    if (i < NN) {
        int dr = g_deg2[i];
        int dc = g_deg_c[i];
        float ir = dr > 0 ? rsqrtf((float)dr) : 0.0f;
        float ic = dc > 0 ? rsqrtf((float)dc) : 0.0f;
        g_dinv_r[i] = ir;
        g_premul[i] = mask[i] ? ic : 0.0f;
        g_dd[i]     = ir * ic;
    }
}

// Fused two-level scans for BOTH CSRs (blocks [0,NB) -> CSR1, [NB,2NB) -> CSR2)
__global__ void scan_block_fused() {
    int bb = blockIdx.x;
    int isP2 = (bb >= NB);
    int b = isP2 ? bb - NB : bb;
    const int* __restrict__ deg = isP2 ? g_deg2  : g_deg1;
    int* __restrict__ rp        = isP2 ? g_rp2   : g_rp1;
    int* __restrict__ part      = isP2 ? g_part2 : g_part1;
    __shared__ int wsum[32];
    int t = threadIdx.x, lane = t & 31, wid = t >> 5;
    int i = b * 1024 + t;
    int v = (i < NN) ? deg[i] : 0;
    int incl = v;
    #pragma unroll
    for (int off = 1; off < 32; off <<= 1) {
        int x = __shfl_up_sync(0xffffffffu, incl, off);
        if (lane >= off) incl += x;
    }
    if (lane == 31) wsum[wid] = incl;
    __syncthreads();
    if (wid == 0) {
        int ws = wsum[lane];
        int wincl = ws;
        #pragma unroll
        for (int off = 1; off < 32; off <<= 1) {
            int x = __shfl_up_sync(0xffffffffu, wincl, off);
            if (lane >= off) wincl += x;
        }
        wsum[lane] = wincl - ws;
    }
    __syncthreads();
    int excl = incl - v + wsum[wid];
    if (i < NN) rp[i] = excl;
    if (t == 1023) part[b] = excl + v;
}

__global__ void scan_part_fused() {
    int t = threadIdx.x;
    if (t == 0) {
        int s = 0;
        for (int b = 0; b < NB; b++) { int v = g_part1[b]; g_part1[b] = s; s += v; }
        g_rp1[NN] = s;
    } else if (t == 32) {
        int s = 0;
        for (int b = 0; b < NB; b++) { int v = g_part2[b]; g_part2[b] = s; s += v; }
        g_rp2[NN] = s;
    }
}

__global__ void scan_add_fused() {
    int bb = blockIdx.x;
    int isP2 = (bb >= NB);
    int b = isP2 ? bb - NB : bb;
    int* __restrict__ rp         = isP2 ? g_rp2   : g_rp1;
    const int* __restrict__ part = isP2 ? g_part2 : g_part1;
    int i = b * 1024 + threadIdx.x;
    if (i < NN) rp[i] += part[b];
}

__global__ void scatter_kernel(const int* __restrict__ row, const int* __restrict__ col,
                               const int* __restrict__ mask) {
    int e = blockIdx.x * blockDim.x + threadIdx.x;
    if (e < NE) {
        int r = row[e], c = col[e];
        int p2 = g_rp2[r] + atomicAdd(&g_cur2[r], 1);
        g_ecol2[p2] = c;
        if (mask[c]) {
            int p1 = g_rp1[r] + atomicAdd(&g_cur1[r], 1);
            g_ecol1[p1] = c;
        }
    }
}

// uh = mask*dinv_c * r0; rh = fp16(r0)
__global__ void init_u_kernel(const float* __restrict__ r0) {
    int i = blockIdx.x * blockDim.x + threadIdx.x;   // float2 index
    if (i < NN * DF / 2) {
        int node = i >> 5;
        float p = g_premul[node];
        float2 r = ((const float2*)r0)[i];
        g_uh[i] = __floats2half2_rn(p * r.x, p * r.y);
        g_rh[i] = __floats2half2_rn(r.x, r.y);
    }
}

// ------ gather core: QUARTER-WARP per row (4 rows/warp), uint4 (16B) loads ------
struct Acc8 { float a0, a1, a2, a3, a4, a5, a6, a7; };

#define QACC(v) \
    { float2 f; \
      f = __half22float2(*(const __half2*)&(v).x); r.a0 += f.x; r.a1 += f.y; \
      f = __half22float2(*(const __half2*)&(v).y); r.a2 += f.x; r.a3 += f.y; \
      f = __half22float2(*(const __half2*)&(v).z); r.a4 += f.x; r.a5 += f.y; \
      f = __half22float2(*(const __half2*)&(v).w); r.a6 += f.x; r.a7 += f.y; }

__device__ __forceinline__ Acc8
row_gather_quarter(const __half2* __restrict__ x, const int* __restrict__ ec,
                   const int* __restrict__ rp, int row, int m) {
    int s = rp[row];
    int n_my = rp[row + 1] - s;
    int t = __shfl_xor_sync(0xffffffffu, n_my, 8);
    int nmax = max(n_my, t);
    t = __shfl_xor_sync(0xffffffffu, nmax, 16);
    nmax = max(nmax, t);
    const char* __restrict__ xb = (const char*)x;
    unsigned moff = m << 4;                       // 16 B per lane
    Acc8 r = {0.f, 0.f, 0.f, 0.f, 0.f, 0.f, 0.f, 0.f};

    for (int j0 = 0; j0 < nmax; j0 += 8) {
        int myidx = j0 + m;
        int c = (myidx < n_my) ? __ldg(&ec[s + myidx]) : 0;
        #pragma unroll
        for (int g = 0; g < 2; g++) {
            int b = j0 + g * 4;
            if (b >= nmax) break;                 // warp-uniform
            int c0 = __shfl_sync(0xffffffffu, c, g * 4 + 0, 8);
            int c1 = __shfl_sync(0xffffffffu, c, g * 4 + 1, 8);
            int c2 = __shfl_sync(0xffffffffu, c, g * 4 + 2, 8);
            int c3 = __shfl_sync(0xffffffffu, c, g * 4 + 3, 8);
            uint4 z = make_uint4(0u, 0u, 0u, 0u);
            uint4 v0 = (b + 0 < n_my) ? __ldg((const uint4*)(xb + (((size_t)c0) << 7) + moff)) : z;
            uint4 v1 = (b + 1 < n_my) ? __ldg((const uint4*)(xb + (((size_t)c1) << 7) + moff)) : z;
            uint4 v2 = (b + 2 < n_my) ? __ldg((const uint4*)(xb + (((size_t)c2) << 7) + moff)) : z;
            uint4 v3 = (b + 3 < n_my) ? __ldg((const uint4*)(xb + (((size_t)c3) << 7) + moff)) : z;
            QACC(v0) QACC(v1) QACC(v2) QACC(v3)
        }
    }
    return r;
}

// hop-1: t1h[row] = dd[row] * sum_{masked e} uh[col_e]
__global__ void __launch_bounds__(64)
hop1_kernel() {
    int w = (blockIdx.x * blockDim.x + threadIdx.x) >> 5;
    if (w >= NN / 4) return;
    int lane = threadIdx.x & 31;
    int m = lane & 7;
    int row = w * 4 + (lane >> 3);
    Acc8 r = row_gather_quarter(g_uh, g_ecol1, g_rp1, row, m);
    float sc = g_dd[row];
    __half2 h0 = __floats2half2_rn(sc * r.a0, sc * r.a1);
    __half2 h1 = __floats2half2_rn(sc * r.a2, sc * r.a3);
    __half2 h2 = __floats2half2_rn(sc * r.a4, sc * r.a5);
    __half2 h3 = __floats2half2_rn(sc * r.a6, sc * r.a7);
    ((uint4*)g_t1h)[row * 8 + m] =
        make_uint4(*(const unsigned*)&h0, *(const unsigned*)&h1,
                   *(const unsigned*)&h2, *(const unsigned*)&h3);
}

// helpers: pack/unpack 8 floats <-> uint4 of half2
__device__ __forceinline__ uint4 pack8h(float a, float b, float c, float d,
                                        float e, float f, float g, float h) {
    __half2 h0 = __floats2half2_rn(a, b);
    __half2 h1 = __floats2half2_rn(c, d);
    __half2 h2 = __floats2half2_rn(e, f);
    __half2 h3 = __floats2half2_rn(g, h);
    return make_uint4(*(const unsigned*)&h0, *(const unsigned*)&h1,
                      *(const unsigned*)&h2, *(const unsigned*)&h3);
}

// hop-2 + RK4 epilogue. v = -dinv_r[row] * sum_e t1h[col_e]
// MODE 1 (k1): acc  = v;  u = rh + 0.5*dt*v      (acc fp16, rh fp16)
// MODE 2 (k2): acc += 2v; u = rh + 0.5*dt*v
// MODE 3 (k3): acc += 2v; u = rh +     dt*v
// MODE 4 (k4): rnext = r + dt/6*(acc+v) [r fp32]; u = rnext; rh = rnext
template <int MODE>
__global__ void __launch_bounds__(64)
hop2_kernel(const float* __restrict__ rin, float* __restrict__ outparam) {
    int w = (blockIdx.x * blockDim.x + threadIdx.x) >> 5;
    if (w >= NN / 4) return;
    int lane = threadIdx.x & 31;
    int m = lane & 7;
    int row = w * 4 + (lane >> 3);
    Acc8 g = row_gather_quarter(g_t1h, g_ecol2, g_rp2, row, m);
    float sr = g_dinv_r[row];
    float v0 = -sr * g.a0, v1 = -sr * g.a1, v2 = -sr * g.a2, v3 = -sr * g.a3;
    float v4 = -sr * g.a4, v5 = -sr * g.a5, v6 = -sr * g.a6, v7 = -sr * g.a7;

    int o4 = row * 8 + m;                         // uint4 index (uh/rh/acch)
    float p = g_premul[row];

    float u0, u1, u2, u3, u4, u5, u6, u7;
    if (MODE == 1) {
        g_acch[o4] = pack8h(v0, v1, v2, v3, v4, v5, v6, v7);
        uint4 rh4 = ((const uint4*)g_rh)[o4];
        float2 fa = __half22float2(*(const __half2*)&rh4.x);
        float2 fb = __half22float2(*(const __half2*)&rh4.y);
        float2 fc = __half22float2(*(const __half2*)&rh4.z);
        float2 fd = __half22float2(*(const __half2*)&rh4.w);
        u0 = fa.x + HALF_DT * v0; u1 = fa.y + HALF_DT * v1;
        u2 = fb.x + HALF_DT * v2; u3 = fb.y + HALF_DT * v3;
        u4 = fc.x + HALF_DT * v4; u5 = fc.y + HALF_DT * v5;
        u6 = fd.x + HALF_DT * v6; u7 = fd.y + HALF_DT * v7;
    } else if (MODE == 2 || MODE == 3) {
        uint4 a4 = g_acch[o4];
        float2 aa = __half22float2(*(const __half2*)&a4.x);
        float2 ab = __half22float2(*(const __half2*)&a4.y);
        float2 ac = __half22float2(*(const __half2*)&a4.z);
        float2 ad = __half22float2(*(const __half2*)&a4.w);
        g_acch[o4] = pack8h(aa.x + 2.f * v0, aa.y + 2.f * v1,
                            ab.x + 2.f * v2, ab.y + 2.f * v3,
                            ac.x + 2.f * v4, ac.y + 2.f * v5,
                            ad.x + 2.f * v6, ad.y + 2.f * v7);
        uint4 rh4 = ((const uint4*)g_rh)[o4];
        float2 fa = __half22float2(*(const __half2*)&rh4.x);
        float2 fb = __half22float2(*(const __half2*)&rh4.y);
        float2 fc = __half22float2(*(const __half2*)&rh4.z);
        float2 fd = __half22float2(*(const __half2*)&rh4.w);
        float cdt = (MODE == 2) ? HALF_DT : DTC;
        u0 = fa.x + cdt * v0; u1 = fa.y + cdt * v1;
        u2 = fb.x + cdt * v2; u3 = fb.y + cdt * v3;
        u4 = fc.x + cdt * v4; u5 = fc.y + cdt * v5;
        u6 = fd.x + cdt * v6; u7 = fd.y + cdt * v7;
    } else {  // MODE 4
        uint4 a4 = g_acch[o4];
        float2 aa = __half22float2(*(const __half2*)&a4.x);
        float2 ab = __half22float2(*(const __half2*)&a4.y);
        float2 ac = __half22float2(*(const __half2*)&a4.z);
        float2 ad = __half22float2(*(const __half2*)&a4.w);
        int oA = row * 16 + 2 * m;                // float4 index (rin/out)
        float4 ra = ((const float4*)rin)[oA];
        float4 rb = ((const float4*)rin)[oA + 1];
        u0 = ra.x + DT6 * (aa.x + v0); u1 = ra.y + DT6 * (aa.y + v1);
        u2 = ra.z + DT6 * (ab.x + v2); u3 = ra.w + DT6 * (ab.y + v3);
        u4 = rb.x + DT6 * (ac.x + v4); u5 = rb.y + DT6 * (ac.y + v5);
        u6 = rb.z + DT6 * (ad.x + v6); u7 = rb.w + DT6 * (ad.y + v7);
        ((float4*)outparam)[oA]     = make_float4(u0, u1, u2, u3);
        ((float4*)outparam)[oA + 1] = make_float4(u4, u5, u6, u7);
        ((uint4*)g_rh)[o4] = pack8h(u0, u1, u2, u3, u4, u5, u6, u7);
    }
    ((uint4*)g_uh)[o4] = pack8h(p * u0, p * u1, p * u2, p * u3,
                                p * u4, p * u5, p * u6, p * u7);
}

// ---------------- launch ----------------
extern "C" void kernel_launch(void* const* d_in, const int* in_sizes, int n_in,
                              void* d_out, int out_size) {
    const float* r0   = (const float*)d_in[0];
    const int*   eidx = (const int*)d_in[1];
    const int*   mask = (const int*)d_in[2];
    const int* row = eidx;
    const int* col = eidx + NE;
    float* out = (float*)d_out;

    // CSR + normalization build (no device-global symbols passed from host!)
    zero_kernel<<<(NN + 255) / 256, 256>>>();
    hist_kernel<<<(NE + 255) / 256, 256>>>(row, col, mask);
    dinv_kernel<<<(NN + 255) / 256, 256>>>(mask);
    scan_block_fused<<<2 * NB, 1024>>>();
    scan_part_fused <<<1, 64>>>();
    scan_add_fused  <<<2 * NB, 1024>>>();
    scatter_kernel  <<<(NE + 255) / 256, 256>>>(row, col, mask);

    // slice 0 = r0; uh = premul * r0; rh = fp16(r0)
    cudaMemcpyAsync(out, r0, (size_t)NN * DF * sizeof(float),
                    cudaMemcpyDeviceToDevice, 0);
    init_u_kernel<<<(NN * DF / 2 + 255) / 256, 256>>>(r0);

    // quarter-warp per row; 64-thread blocks (small tail)
    const int blocks = (NN / 4 * 32 + 63) / 64;

    for (int step = 0; step < 5; step++) {
        const float* r = out + (size_t)step * NN * DF;
        float* rnext   = out + (size_t)(step + 1) * NN * DF;

        hop1_kernel   <<<blocks, 64>>>();
        hop2_kernel<1><<<blocks, 64>>>(r, nullptr);
        hop1_kernel   <<<blocks, 64>>>();
        hop2_kernel<2><<<blocks, 64>>>(r, nullptr);
        hop1_kernel   <<<blocks, 64>>>();
        hop2_kernel<3><<<blocks, 64>>>(r, nullptr);
        hop1_kernel   <<<blocks, 64>>>();
        hop2_kernel<4><<<blocks, 64>>>(r, rnext);
    }
}